// round 12
// baseline (speedup 1.0000x reference)
#include <cuda_runtime.h>
#include <cuda_fp16.h>
#include <cstdint>

// Problem constants
#define N_NODES   50000
#define N_EDGES   800000
#define N_TOT     850000      // edges + self loops
#define IN_CH     128
#define HID       256
#define N_GRAPHS  512
#define SCAN_NB   196         // ceil(50000/256)
#define NC4       (N_NODES * IN_CH / 4)   // 1,600,000 float4 chunks of x
#define NBLK      391         // ceil(50000/128) row blocks

// ---------------- scratch (device globals; no allocation allowed) -------------
__device__ __half g_xh[(size_t)N_NODES * IN_CH];   // x in fp16
__device__ __half g_hB[(size_t)N_NODES * HID];     // layer outputs (ping)
__device__ __half g_hC[(size_t)N_NODES * HID];     // layer outputs (pong)
__device__ __half g_w0t[HID * IN_CH];              // W0^T [256][128] fp16
__device__ __half g_w1t[HID * HID];                // W1^T
__device__ __half g_w2t[HID * HID];                // W2^T
__device__ int   g_deg[N_NODES];                   // zero at launch start & end
__device__ float g_dinv[N_NODES];
__device__ int   g_rowptr[N_NODES + 1];
__device__ int   g_cursor[N_NODES];
__device__ int   g_col[N_TOT];
__device__ float g_w[N_TOT];
__device__ int   g_gstart[N_GRAPHS + 1];
__device__ int   g_psum[SCAN_NB + 4];

// ---------------- fused elementwise setup + edge count -------------------------
// conv_x + W transposes + graph ranges + degree count (g_deg starts at zero:
// zero-init on first call, re-zeroed by scan_write_kernel every launch).
__global__ void setup_kernel(const float* __restrict__ x,
                             const float* __restrict__ W0,
                             const float* __restrict__ W1,
                             const float* __restrict__ W2,
                             const int* __restrict__ dst,
                             const int* __restrict__ batch) {
    int i = blockIdx.x * blockDim.x + threadIdx.x;
    if (i < NC4) {
        float4 v = *(const float4*)(x + (size_t)i * 4);
        __half2 h0 = __float22half2_rn(make_float2(v.x, v.y));
        __half2 h1 = __float22half2_rn(make_float2(v.z, v.w));
        *(uint2*)(&g_xh[(size_t)i * 4]) = make_uint2(
            *(const unsigned*)&h0, *(const unsigned*)&h1);
    }
    if (i < N_EDGES) atomicAdd(&g_deg[dst[i]], 1);
    if (i < HID * IN_CH) {                              // W0^T
        int n = i / IN_CH, k = i % IN_CH;
        g_w0t[i] = __float2half(W0[(size_t)k * HID + n]);
    }
    if (i < HID * HID) {                                // W1^T, W2^T
        int n = i / HID, k = i % HID;
        g_w1t[i] = __float2half(W1[(size_t)k * HID + n]);
        g_w2t[i] = __float2half(W2[(size_t)k * HID + n]);
    }
    if (i <= N_GRAPHS) {                                // graph ranges
        int lo = 0, hi = N_NODES;
        while (lo < hi) {
            int mid = (lo + hi) >> 1;
            if (batch[mid] < i) lo = mid + 1; else hi = mid;
        }
        g_gstart[i] = lo;
    }
}

// block sums for scan + dinv.  Effective degree = g_deg + 1 (self loop).
__global__ void bsum_dinv_kernel() {
    int b = blockIdx.x, t = threadIdx.x;
    int idx = b * 256 + t;
    int d = (idx < N_NODES) ? (g_deg[idx] + 1) : 0;
    if (idx < N_NODES) g_dinv[idx] = rsqrtf((float)d);
    int v = d;
    #pragma unroll
    for (int off = 16; off > 0; off >>= 1)
        v += __shfl_down_sync(0xffffffffu, v, off);
    __shared__ int ws[8];
    if ((t & 31) == 0) ws[t >> 5] = v;
    __syncthreads();
    if (t == 0) {
        int s = 0;
        #pragma unroll
        for (int i = 0; i < 8; i++) s += ws[i];
        g_psum[b] = s;
    }
}

// per-block scan; block offset = inline sum of partials < b; resets g_deg.
__global__ void scan_write_kernel() {
    int b = blockIdx.x, t = threadIdx.x, lane = t & 31, w = t >> 5;
    int contrib = (t < b) ? g_psum[t] : 0;
    #pragma unroll
    for (int off = 16; off > 0; off >>= 1)
        contrib += __shfl_down_sync(0xffffffffu, contrib, off);
    __shared__ int rs[8];
    __shared__ int off_s;
    if ((t & 31) == 0) rs[t >> 5] = contrib;
    __syncthreads();
    if (t == 0) {
        int s = 0;
        #pragma unroll
        for (int i = 0; i < 8; i++) s += rs[i];
        off_s = s;
    }
    int idx = b * 256 + t;
    int v = (idx < N_NODES) ? (g_deg[idx] + 1) : 0;
    if (idx < N_NODES) g_deg[idx] = 0;      // restore invariant for next launch
    int x = v;
    #pragma unroll
    for (int off = 1; off < 32; off <<= 1) {
        int y = __shfl_up_sync(0xffffffffu, x, off);
        if (lane >= off) x += y;
    }
    __shared__ int wsum[8];
    if (lane == 31) wsum[w] = x;
    __syncthreads();
    if (t == 0) {
        int run = 0;
        #pragma unroll
        for (int i = 0; i < 8; i++) { int tmp = wsum[i]; wsum[i] = run; run += tmp; }
    }
    __syncthreads();
    int excl = off_s + x + wsum[w] - v;
    if (idx < N_NODES) { g_rowptr[idx] = excl; g_cursor[idx] = excl; }
    if (b == 0 && t == 0) g_rowptr[N_NODES] = N_TOT;
}

// edges + self loops in one launch
__global__ void place_all_kernel(const int* __restrict__ src,
                                 const int* __restrict__ dst) {
    int e = blockIdx.x * blockDim.x + threadIdx.x;
    if (e < N_EDGES) {
        int s = src[e], d = dst[e];
        int pos = atomicAdd(&g_cursor[d], 1);
        g_col[pos] = s;
        g_w[pos]   = g_dinv[s] * g_dinv[d];
    } else {
        int v = e - N_EDGES;
        if (v < N_NODES) {
            int pos = atomicAdd(&g_cursor[v], 1);
            g_col[pos] = v;
            float dv = g_dinv[v];
            g_w[pos]  = dv * dv;
        }
    }
}

// ---------------- fused aggregate + GEMM layer ---------------------------------
// Block = 128 output rows x full N=256.  Phase 1: gather/aggregate the block's
// 128 rows into smem (fp16, fp32 accum) while cp.async prefetches the full
// W^T tile.  Phase 2: MMA GEMM from smem, bias+relu epilogue to gmem fp16.
#define MMA_F16(d, a0, a1, a2, a3, b0, b1)                                    \
    asm volatile(                                                             \
        "mma.sync.aligned.m16n8k16.row.col.f32.f16.f16.f32 "                  \
        "{%0,%1,%2,%3}, {%4,%5,%6,%7}, {%8,%9}, {%0,%1,%2,%3};"               \
        : "+f"((d)[0]), "+f"((d)[1]), "+f"((d)[2]), "+f"((d)[3])              \
        : "r"(a0), "r"(a1), "r"(a2), "r"(a3), "r"(b0), "r"(b1))

__device__ __forceinline__ void cpa16(void* sm, const void* gm) {
    uint32_t sa = (uint32_t)__cvta_generic_to_shared(sm);
    asm volatile("cp.async.cg.shared.global [%0], [%1], 16;" :: "r"(sa), "l"(gm));
}

template <int KD>
__global__ void __launch_bounds__(512, 1)
fused_layer_kernel(const __half* __restrict__ xin, const __half* __restrict__ Wt,
                   const float* __restrict__ bias, __half* __restrict__ out) {
    extern __shared__ __half smem[];
    const int STR = KD + 8;
    __half* As = smem;                   // [128][STR]
    __half* Bs = smem + 128 * STR;       // [256][STR]
    int tid = threadIdx.x, lane = tid & 31, wid = tid >> 5;
    int bm = blockIdx.x;

    // ---- prefetch full weight tile (hidden behind aggregation) ----
    const int CH = KD / 8;               // 16B chunks per weight row
    for (int c = tid; c < HID * CH; c += 512) {
        int n = c / CH, kc = (c % CH) * 8;
        cpa16(&Bs[n * STR + kc], Wt + (size_t)n * KD + kc);
    }
    asm volatile("cp.async.commit_group;");

    // ---- phase 1: aggregate 8 rows per warp into As ----
    constexpr int V = KD / 32;           // halfs per lane (4 or 8)
    for (int j = 0; j < 8; j++) {
        int rloc = wid * 8 + j;
        int row = bm * 128 + rloc;
        float acc[V];
        #pragma unroll
        for (int q = 0; q < V; q++) acc[q] = 0.f;

        if (row < N_NODES) {
            int s = g_rowptr[row], e = g_rowptr[row + 1];
            auto accum = [&](int cidx, float wt) {
                const __half* p = xin + (size_t)cidx * KD + lane * V;
                if constexpr (V == 4) {
                    uint2 u = __ldg((const uint2*)p);
                    __half2 h0 = *(__half2*)&u.x, h1 = *(__half2*)&u.y;
                    float2 f0 = __half22float2(h0), f1 = __half22float2(h1);
                    acc[0] += wt * f0.x; acc[1] += wt * f0.y;
                    acc[2] += wt * f1.x; acc[3] += wt * f1.y;
                } else {
                    uint4 u = __ldg((const uint4*)p);
                    __half2 h0 = *(__half2*)&u.x, h1 = *(__half2*)&u.y;
                    __half2 h2 = *(__half2*)&u.z, h3 = *(__half2*)&u.w;
                    float2 f0 = __half22float2(h0), f1 = __half22float2(h1);
                    float2 f2 = __half22float2(h2), f3 = __half22float2(h3);
                    acc[0] += wt * f0.x; acc[1] += wt * f0.y;
                    acc[2] += wt * f1.x; acc[3] += wt * f1.y;
                    acc[4] += wt * f2.x; acc[5] += wt * f2.y;
                    acc[6] += wt * f3.x; acc[7] += wt * f3.y;
                }
            };
            int i = s;
            for (; i + 4 <= e; i += 4) {
                int   c0 = g_col[i],   c1 = g_col[i+1];
                int   c2 = g_col[i+2], c3 = g_col[i+3];
                float w0 = g_w[i],     w1 = g_w[i+1];
                float w2 = g_w[i+2],   w3 = g_w[i+3];
                accum(c0, w0); accum(c1, w1); accum(c2, w2); accum(c3, w3);
            }
            for (; i < e; i++) accum(g_col[i], g_w[i]);
        }

        __half* arow = &As[rloc * STR + lane * V];
        if constexpr (V == 4) {
            __half2 o0 = __float22half2_rn(make_float2(acc[0], acc[1]));
            __half2 o1 = __float22half2_rn(make_float2(acc[2], acc[3]));
            *(uint2*)arow = make_uint2(*(unsigned*)&o0, *(unsigned*)&o1);
        } else {
            __half2 o0 = __float22half2_rn(make_float2(acc[0], acc[1]));
            __half2 o1 = __float22half2_rn(make_float2(acc[2], acc[3]));
            __half2 o2 = __float22half2_rn(make_float2(acc[4], acc[5]));
            __half2 o3 = __float22half2_rn(make_float2(acc[6], acc[7]));
            *(uint4*)arow = make_uint4(*(unsigned*)&o0, *(unsigned*)&o1,
                                       *(unsigned*)&o2, *(unsigned*)&o3);
        }
    }

    asm volatile("cp.async.wait_group 0;");
    __syncthreads();

    // ---- phase 2: GEMM from smem.  16 warps = 4x4 grid of 32x64 tiles ----
    int wm = (wid >> 2) * 32;            // 0,32,64,96
    int wn = (wid & 3) * 64;             // 0,64,128,192
    int g = lane >> 2, t = lane & 3;

    float acc[2][8][4];
    #pragma unroll
    for (int mt = 0; mt < 2; mt++)
        #pragma unroll
        for (int nt = 0; nt < 8; nt++)
            #pragma unroll
            for (int q = 0; q < 4; q++) acc[mt][nt][q] = 0.f;

    #pragma unroll
    for (int ks = 0; ks < KD / 16; ks++) {
        int kbase = ks * 16 + 2 * t;
        uint a0[2], a1[2], a2[2], a3[2];
        #pragma unroll
        for (int mt = 0; mt < 2; mt++) {
            int r = wm + mt * 16 + g;
            a0[mt] = *(const uint*)&As[r * STR + kbase];
            a1[mt] = *(const uint*)&As[(r + 8) * STR + kbase];
            a2[mt] = *(const uint*)&As[r * STR + kbase + 8];
            a3[mt] = *(const uint*)&As[(r + 8) * STR + kbase + 8];
        }
        uint b0[8], b1[8];
        #pragma unroll
        for (int nt = 0; nt < 8; nt++) {
            int n = wn + nt * 8 + g;
            b0[nt] = *(const uint*)&Bs[n * STR + kbase];
            b1[nt] = *(const uint*)&Bs[n * STR + kbase + 8];
        }
        #pragma unroll
        for (int mt = 0; mt < 2; mt++)
            #pragma unroll
            for (int nt = 0; nt < 8; nt++)
                MMA_F16(acc[mt][nt], a0[mt], a1[mt], a2[mt], a3[mt],
                        b0[nt], b1[nt]);
    }

    // ---- epilogue: bias + relu -> fp16, guarded stores ----
    #pragma unroll
    for (int mt = 0; mt < 2; mt++) {
        int row0 = bm * 128 + wm + mt * 16 + g;
        #pragma unroll
        for (int nt = 0; nt < 8; nt++) {
            int col = wn + nt * 8 + 2 * t;
            float2 bb = *(const float2*)(bias + col);
            __half2 o0 = __float22half2_rn(make_float2(
                fmaxf(acc[mt][nt][0] + bb.x, 0.f),
                fmaxf(acc[mt][nt][1] + bb.y, 0.f)));
            __half2 o1 = __float22half2_rn(make_float2(
                fmaxf(acc[mt][nt][2] + bb.x, 0.f),
                fmaxf(acc[mt][nt][3] + bb.y, 0.f)));
            if (row0 < N_NODES)
                *(unsigned*)(out + (size_t)row0 * HID + col) = *(unsigned*)&o0;
            if (row0 + 8 < N_NODES)
                *(unsigned*)(out + (size_t)(row0 + 8) * HID + col) = *(unsigned*)&o1;
        }
    }
}

// ---------------- pooling (128 threads x 2 channels via half2) -----------------
__global__ void pool_kernel(const __half* __restrict__ h, float* __restrict__ out) {
    int gph = blockIdx.x;
    int c2 = threadIdx.x;                 // 128 half2 channels
    int s = g_gstart[gph], e = g_gstart[gph + 1];
    float accx = 0.f, accy = 0.f;
    for (int v = s; v < e; v++) {
        __half2 hv = *(const __half2*)(h + (size_t)v * HID + c2 * 2);
        float2 f = __half22float2(hv);
        accx += f.x; accy += f.y;
    }
    *(float2*)(out + (size_t)gph * HID + c2 * 2) = make_float2(accx, accy);
}

// ---------------- launch -------------------------------------------------------
extern "C" void kernel_launch(void* const* d_in, const int* in_sizes, int n_in,
                              void* d_out, int out_size) {
    const float* x   = (const float*)d_in[0];
    const float* W0  = (const float*)d_in[1];
    const float* b0  = (const float*)d_in[2];
    const float* W1  = (const float*)d_in[3];
    const float* b1  = (const float*)d_in[4];
    const float* W2  = (const float*)d_in[5];
    const float* b2  = (const float*)d_in[6];
    const int*   ei  = (const int*)d_in[7];
    const int*   bat = (const int*)d_in[8];
    float* out = (float*)d_out;

    const int* src = ei;
    const int* dst = ei + N_EDGES;

    __half* xh;  cudaGetSymbolAddress((void**)&xh,  g_xh);
    __half* hB;  cudaGetSymbolAddress((void**)&hB,  g_hB);
    __half* hC;  cudaGetSymbolAddress((void**)&hC,  g_hC);
    __half* w0t; cudaGetSymbolAddress((void**)&w0t, g_w0t);
    __half* w1t; cudaGetSymbolAddress((void**)&w1t, g_w1t);
    __half* w2t; cudaGetSymbolAddress((void**)&w2t, g_w2t);

    const int SM128 = (128 + 256) * (IN_CH + 8) * 2;   // 104,448 B
    const int SM256 = (128 + 256) * (HID + 8) * 2;     // 202,752 B
    cudaFuncSetAttribute(fused_layer_kernel<IN_CH>,
                         cudaFuncAttributeMaxDynamicSharedMemorySize, SM128);
    cudaFuncSetAttribute(fused_layer_kernel<HID>,
                         cudaFuncAttributeMaxDynamicSharedMemorySize, SM256);

    // prep: setup(+count) -> bsum+dinv -> scan(+deg reset) -> place
    setup_kernel<<<(NC4 + 255) / 256, 256>>>(x, W0, W1, W2, dst, bat);
    bsum_dinv_kernel<<<SCAN_NB, 256>>>();
    scan_write_kernel<<<SCAN_NB, 256>>>();
    place_all_kernel<<<(N_TOT + 255) / 256, 256>>>(src, dst);

    // fused layers
    fused_layer_kernel<IN_CH><<<NBLK, 512, SM128>>>(xh, w0t, b0, hB);
    fused_layer_kernel<HID><<<NBLK, 512, SM256>>>(hB, w1t, b1, hC);
    fused_layer_kernel<HID><<<NBLK, 512, SM256>>>(hC, w2t, b2, hB);

    // pool
    pool_kernel<<<N_GRAPHS, 128>>>(hB, out);
}

// round 13
// speedup vs baseline: 1.3307x; 1.3307x over previous
#include <cuda_runtime.h>
#include <cuda_fp16.h>
#include <cstdint>

// Problem constants
#define N_NODES   50000
#define N_EDGES   800000
#define N_TOT     850000      // edges + self loops
#define IN_CH     128
#define HID       256
#define N_GRAPHS  512
#define M_PAD     50048       // 391 * 128
#define SCAN_NB   196         // ceil(50000/256)
#define NC4       (N_NODES * IN_CH / 4)   // 1,600,000 float4 chunks of x

// ---------------- scratch (device globals; no allocation allowed) -------------
__device__ __half g_xh[(size_t)N_NODES * IN_CH];   // dinv-scaled x in fp16
__device__ __half g_hA[(size_t)M_PAD * IN_CH];     // aggregated input
__device__ __half g_hB[(size_t)M_PAD * HID];       // gemm outputs (ping)
__device__ __half g_hC[(size_t)M_PAD * HID];       // aggregated hidden (pong)
__device__ __half g_w0t[HID * IN_CH];              // W0^T [256][128] fp16
__device__ __half g_w1t[HID * HID];                // W1^T
__device__ __half g_w2t[HID * HID];                // W2^T
__device__ int   g_deg[N_NODES];                   // zero at launch start & end
__device__ float g_dinv[N_NODES];
__device__ int   g_rowptr[N_NODES + 1];
__device__ int   g_cursor[N_NODES];
__device__ int   g_col[N_TOT];
__device__ int   g_gstart[N_GRAPHS + 1];
__device__ int   g_psum[SCAN_NB + 4];

// ---------------- setup: degree count + W transposes + graph ranges ------------
// g_deg starts at zero (zero-init first launch; re-zeroed by scan_write).
__global__ void setup_kernel(const float* __restrict__ W0,
                             const float* __restrict__ W1,
                             const float* __restrict__ W2,
                             const int* __restrict__ dst,
                             const int* __restrict__ batch) {
    int i = blockIdx.x * blockDim.x + threadIdx.x;
    if (i < N_EDGES) atomicAdd(&g_deg[dst[i]], 1);
    if (i < HID * IN_CH) {                              // W0^T
        int n = i / IN_CH, k = i % IN_CH;
        g_w0t[i] = __float2half(W0[(size_t)k * HID + n]);
    }
    if (i < HID * HID) {                                // W1^T, W2^T
        int n = i / HID, k = i % HID;
        g_w1t[i] = __float2half(W1[(size_t)k * HID + n]);
        g_w2t[i] = __float2half(W2[(size_t)k * HID + n]);
    }
    if (i <= N_GRAPHS) {                                // graph ranges
        int lo = 0, hi = N_NODES;
        while (lo < hi) {
            int mid = (lo + hi) >> 1;
            if (batch[mid] < i) lo = mid + 1; else hi = mid;
        }
        g_gstart[i] = lo;
    }
}

// block sums for scan + dinv.  Effective degree = g_deg + 1 (self loop).
__global__ void bsum_dinv_kernel() {
    int b = blockIdx.x, t = threadIdx.x;
    int idx = b * 256 + t;
    int d = (idx < N_NODES) ? (g_deg[idx] + 1) : 0;
    if (idx < N_NODES) g_dinv[idx] = rsqrtf((float)d);
    int v = d;
    #pragma unroll
    for (int off = 16; off > 0; off >>= 1)
        v += __shfl_down_sync(0xffffffffu, v, off);
    __shared__ int ws[8];
    if ((t & 31) == 0) ws[t >> 5] = v;
    __syncthreads();
    if (t == 0) {
        int s = 0;
        #pragma unroll
        for (int i = 0; i < 8; i++) s += ws[i];
        g_psum[b] = s;
    }
}

// per-block scan; block offset = inline sum of partials < b; resets g_deg.
__global__ void scan_write_kernel() {
    int b = blockIdx.x, t = threadIdx.x, lane = t & 31, w = t >> 5;
    int contrib = (t < b) ? g_psum[t] : 0;
    #pragma unroll
    for (int off = 16; off > 0; off >>= 1)
        contrib += __shfl_down_sync(0xffffffffu, contrib, off);
    __shared__ int rs[8];
    __shared__ int off_s;
    if ((t & 31) == 0) rs[t >> 5] = contrib;
    __syncthreads();
    if (t == 0) {
        int s = 0;
        #pragma unroll
        for (int i = 0; i < 8; i++) s += rs[i];
        off_s = s;
    }
    int idx = b * 256 + t;
    int v = (idx < N_NODES) ? (g_deg[idx] + 1) : 0;
    if (idx < N_NODES) g_deg[idx] = 0;      // restore invariant for next launch
    int x = v;
    #pragma unroll
    for (int off = 1; off < 32; off <<= 1) {
        int y = __shfl_up_sync(0xffffffffu, x, off);
        if (lane >= off) x += y;
    }
    __shared__ int wsum[8];
    if (lane == 31) wsum[w] = x;
    __syncthreads();
    if (t == 0) {
        int run = 0;
        #pragma unroll
        for (int i = 0; i < 8; i++) { int tmp = wsum[i]; wsum[i] = run; run += tmp; }
    }
    __syncthreads();
    int excl = off_s + x + wsum[w] - v;
    if (idx < N_NODES) { g_rowptr[idx] = excl; g_cursor[idx] = excl; }
    if (b == 0 && t == 0) g_rowptr[N_NODES] = N_TOT;
}

// edges + self loops placement (col only) + dinv-scaled x conversion, one launch
__global__ void place_conv_kernel(const int* __restrict__ src,
                                  const int* __restrict__ dst,
                                  const float* __restrict__ x) {
    int i = blockIdx.x * blockDim.x + threadIdx.x;
    if (i < N_TOT) {
        if (i < N_EDGES) {
            int s = src[i], d = dst[i];
            int pos = atomicAdd(&g_cursor[d], 1);
            g_col[pos] = s;
        } else {
            int v = i - N_EDGES;
            int pos = atomicAdd(&g_cursor[v], 1);
            g_col[pos] = v;
        }
    }
    if (i < NC4) {                       // y[v] = dinv[v] * x[v]  -> fp16
        int row = i >> 5;                // 32 float4 chunks per 128-ch row
        float s = g_dinv[row];
        float4 v = *(const float4*)(x + (size_t)i * 4);
        __half2 h0 = __float22half2_rn(make_float2(v.x * s, v.y * s));
        __half2 h1 = __float22half2_rn(make_float2(v.z * s, v.w * s));
        *(uint2*)(&g_xh[(size_t)i * 4]) = make_uint2(
            *(const unsigned*)&h0, *(const unsigned*)&h1);
    }
}

// ---------------- aggregation: out[v] = dinv[v] * sum_{col} y[col] -------------
template <int C>
__global__ void __launch_bounds__(256)
aggregate_h_kernel(const __half* __restrict__ x, __half* __restrict__ out) {
    int warp = (blockIdx.x * blockDim.x + threadIdx.x) >> 5;
    int lane = threadIdx.x & 31;
    if (warp >= N_NODES) return;
    constexpr int V = C / 32;                        // halfs per lane: 4 or 8
    float acc[V];
    #pragma unroll
    for (int q = 0; q < V; q++) acc[q] = 0.f;
    int s = g_rowptr[warp], e = g_rowptr[warp + 1];

    auto accum = [&](int cidx) {
        const __half* p = x + (size_t)cidx * C + lane * V;
        if constexpr (V == 4) {
            uint2 u = __ldg((const uint2*)p);
            __half2 h0 = *(__half2*)&u.x, h1 = *(__half2*)&u.y;
            float2 f0 = __half22float2(h0), f1 = __half22float2(h1);
            acc[0] += f0.x; acc[1] += f0.y;
            acc[2] += f1.x; acc[3] += f1.y;
        } else {
            uint4 u = __ldg((const uint4*)p);
            __half2 h0 = *(__half2*)&u.x, h1 = *(__half2*)&u.y;
            __half2 h2 = *(__half2*)&u.z, h3 = *(__half2*)&u.w;
            float2 f0 = __half22float2(h0), f1 = __half22float2(h1);
            float2 f2 = __half22float2(h2), f3 = __half22float2(h3);
            acc[0] += f0.x; acc[1] += f0.y;
            acc[2] += f1.x; acc[3] += f1.y;
            acc[4] += f2.x; acc[5] += f2.y;
            acc[6] += f3.x; acc[7] += f3.y;
        }
    };

    int i = s;
    for (; i + 4 <= e; i += 4) {
        int c0 = g_col[i], c1 = g_col[i+1], c2 = g_col[i+2], c3 = g_col[i+3];
        accum(c0); accum(c1); accum(c2); accum(c3);
    }
    for (; i < e; i++) accum(g_col[i]);

    float sc = g_dinv[warp];
    __half* orow = out + (size_t)warp * C + lane * V;
    if constexpr (V == 4) {
        __half2 o0 = __float22half2_rn(make_float2(acc[0] * sc, acc[1] * sc));
        __half2 o1 = __float22half2_rn(make_float2(acc[2] * sc, acc[3] * sc));
        *(uint2*)orow = make_uint2(*(unsigned*)&o0, *(unsigned*)&o1);
    } else {
        __half2 o0 = __float22half2_rn(make_float2(acc[0] * sc, acc[1] * sc));
        __half2 o1 = __float22half2_rn(make_float2(acc[2] * sc, acc[3] * sc));
        __half2 o2 = __float22half2_rn(make_float2(acc[4] * sc, acc[5] * sc));
        __half2 o3 = __float22half2_rn(make_float2(acc[6] * sc, acc[7] * sc));
        *(uint4*)orow = make_uint4(*(unsigned*)&o0, *(unsigned*)&o1,
                                   *(unsigned*)&o2, *(unsigned*)&o3);
    }
}

// ---------------- GEMM: fp16 MMA, cp.async double-buffered ---------------------
// SCALED=true: store dinv[row]*relu(acc+b) (feeds next aggregation).
#define BM 128
#define BN 128
#define BKH 32
#define HSTR 40   // half stride (80 B, 16B-aligned, conflict-free fragment LDS)

#define MMA_F16(d, a0, a1, a2, a3, b0, b1)                                    \
    asm volatile(                                                             \
        "mma.sync.aligned.m16n8k16.row.col.f32.f16.f16.f32 "                  \
        "{%0,%1,%2,%3}, {%4,%5,%6,%7}, {%8,%9}, {%0,%1,%2,%3};"               \
        : "+f"((d)[0]), "+f"((d)[1]), "+f"((d)[2]), "+f"((d)[3])              \
        : "r"(a0), "r"(a1), "r"(a2), "r"(a3), "r"(b0), "r"(b1))

__device__ __forceinline__ void cpa16(void* sm, const void* gm) {
    uint32_t sa = (uint32_t)__cvta_generic_to_shared(sm);
    asm volatile("cp.async.cg.shared.global [%0], [%1], 16;" :: "r"(sa), "l"(gm));
}

template <bool SCALED>
__global__ void __launch_bounds__(256)
gemm_f16_bias_relu(const __half* __restrict__ A, const __half* __restrict__ Wt,
                   const float* __restrict__ bias, __half* __restrict__ C,
                   int K, int N) {
    __shared__ __align__(16) __half As[2][BM][HSTR];   // [stage][m][k]
    __shared__ __align__(16) __half Bs[2][BN][HSTR];   // [stage][n][k]
    int tid = threadIdx.x, lane = tid & 31, wid = tid >> 5;
    int wm = (wid >> 2) * 64;            // 0 or 64
    int wn = (wid & 3) * 32;             // 0..96
    int g = lane >> 2;                   // 0..7
    int t = lane & 3;                    // 0..3

    float acc[4][4][4];
    #pragma unroll
    for (int i = 0; i < 4; i++)
        #pragma unroll
        for (int j = 0; j < 4; j++)
            #pragma unroll
            for (int q = 0; q < 4; q++) acc[i][j][q] = 0.f;

    const __half* Ablk = A + (size_t)blockIdx.y * BM * K;
    const __half* Wblk = Wt + (size_t)blockIdx.x * BN * K;

    int ldr = tid >> 1;                  // 0..127
    int ldc = (tid & 1) * 16;            // 0 or 16 (halfs)

    int niter = K / BKH;

    auto issue = [&](int it) {
        int st = it & 1;
        int k0 = it * BKH;
        const __half* ap = Ablk + (size_t)ldr * K + k0 + ldc;
        cpa16(&As[st][ldr][ldc],     ap);
        cpa16(&As[st][ldr][ldc + 8], ap + 8);
        const __half* bp = Wblk + (size_t)ldr * K + k0 + ldc;
        cpa16(&Bs[st][ldr][ldc],     bp);
        cpa16(&Bs[st][ldr][ldc + 8], bp + 8);
        asm volatile("cp.async.commit_group;");
    };

    issue(0);
    for (int it = 0; it < niter; it++) {
        if (it + 1 < niter) {
            issue(it + 1);
            asm volatile("cp.async.wait_group 1;");
        } else {
            asm volatile("cp.async.wait_group 0;");
        }
        __syncthreads();
        int st = it & 1;
        #pragma unroll
        for (int kk = 0; kk < BKH; kk += 16) {
            int kbase = kk + 2 * t;
            uint a0[4], a1[4], a2[4], a3[4];
            #pragma unroll
            for (int mt = 0; mt < 4; mt++) {
                int r = wm + mt * 16 + g;
                a0[mt] = *(const uint*)&As[st][r    ][kbase];
                a1[mt] = *(const uint*)&As[st][r + 8][kbase];
                a2[mt] = *(const uint*)&As[st][r    ][kbase + 8];
                a3[mt] = *(const uint*)&As[st][r + 8][kbase + 8];
            }
            uint b0[4], b1[4];
            #pragma unroll
            for (int nt = 0; nt < 4; nt++) {
                int n = wn + nt * 8 + g;
                b0[nt] = *(const uint*)&Bs[st][n][kbase];
                b1[nt] = *(const uint*)&Bs[st][n][kbase + 8];
            }
            #pragma unroll
            for (int mt = 0; mt < 4; mt++)
                #pragma unroll
                for (int nt = 0; nt < 4; nt++)
                    MMA_F16(acc[mt][nt], a0[mt], a1[mt], a2[mt], a3[mt],
                            b0[nt], b1[nt]);
        }
        __syncthreads();
    }

    // epilogue: bias + relu (+ optional dinv row scale), fp16 stores
    #pragma unroll
    for (int mt = 0; mt < 4; mt++) {
        int row0 = blockIdx.y * BM + wm + mt * 16 + g;
        float s0 = 1.f, s1 = 1.f;
        if (SCALED) {
            s0 = (row0     < N_NODES) ? g_dinv[row0]     : 0.f;
            s1 = (row0 + 8 < N_NODES) ? g_dinv[row0 + 8] : 0.f;
        }
        #pragma unroll
        for (int nt = 0; nt < 4; nt++) {
            int col = blockIdx.x * BN + wn + nt * 8 + 2 * t;
            float2 bb = *(const float2*)(bias + col);
            __half2 o0 = __float22half2_rn(make_float2(
                fmaxf(acc[mt][nt][0] + bb.x, 0.f) * s0,
                fmaxf(acc[mt][nt][1] + bb.y, 0.f) * s0));
            __half2 o1 = __float22half2_rn(make_float2(
                fmaxf(acc[mt][nt][2] + bb.x, 0.f) * s1,
                fmaxf(acc[mt][nt][3] + bb.y, 0.f) * s1));
            *(unsigned*)(C + (size_t)row0 * N + col)       = *(unsigned*)&o0;
            *(unsigned*)(C + (size_t)(row0 + 8) * N + col) = *(unsigned*)&o1;
        }
    }
}

// ---------------- pooling (128 threads x 2 channels via half2) -----------------
__global__ void pool_kernel(const __half* __restrict__ h, float* __restrict__ out) {
    int gph = blockIdx.x;
    int c2 = threadIdx.x;                 // 128 half2 channels
    int s = g_gstart[gph], e = g_gstart[gph + 1];
    float accx = 0.f, accy = 0.f;
    for (int v = s; v < e; v++) {
        __half2 hv = *(const __half2*)(h + (size_t)v * HID + c2 * 2);
        float2 f = __half22float2(hv);
        accx += f.x; accy += f.y;
    }
    *(float2*)(out + (size_t)gph * HID + c2 * 2) = make_float2(accx, accy);
}

// ---------------- launch -------------------------------------------------------
extern "C" void kernel_launch(void* const* d_in, const int* in_sizes, int n_in,
                              void* d_out, int out_size) {
    const float* x   = (const float*)d_in[0];
    const float* W0  = (const float*)d_in[1];
    const float* b0  = (const float*)d_in[2];
    const float* W1  = (const float*)d_in[3];
    const float* b1  = (const float*)d_in[4];
    const float* W2  = (const float*)d_in[5];
    const float* b2  = (const float*)d_in[6];
    const int*   ei  = (const int*)d_in[7];
    const int*   bat = (const int*)d_in[8];
    float* out = (float*)d_out;

    const int* src = ei;
    const int* dst = ei + N_EDGES;

    __half* xh;  cudaGetSymbolAddress((void**)&xh,  g_xh);
    __half* hA;  cudaGetSymbolAddress((void**)&hA,  g_hA);
    __half* hB;  cudaGetSymbolAddress((void**)&hB,  g_hB);
    __half* hC;  cudaGetSymbolAddress((void**)&hC,  g_hC);
    __half* w0t; cudaGetSymbolAddress((void**)&w0t, g_w0t);
    __half* w1t; cudaGetSymbolAddress((void**)&w1t, g_w1t);
    __half* w2t; cudaGetSymbolAddress((void**)&w2t, g_w2t);

    // prep: setup(count+Wt+ranges) -> bsum+dinv -> scan(+deg reset) -> place+conv
    setup_kernel<<<(N_EDGES + 255) / 256, 256>>>(W0, W1, W2, dst, bat);
    bsum_dinv_kernel<<<SCAN_NB, 256>>>();
    scan_write_kernel<<<SCAN_NB, 256>>>();
    place_conv_kernel<<<(NC4 + 255) / 256, 256>>>(src, dst, x);

    dim3 gemm_grid(HID / BN, M_PAD / BM);   // (2, 391)
    int agg_blocks = (N_NODES * 32 + 255) / 256;

    // layer 0
    aggregate_h_kernel<IN_CH><<<agg_blocks, 256>>>(xh, hA);
    gemm_f16_bias_relu<true><<<gemm_grid, 256>>>(hA, w0t, b0, hB, IN_CH, HID);
    // layer 1
    aggregate_h_kernel<HID><<<agg_blocks, 256>>>(hB, hC);
    gemm_f16_bias_relu<true><<<gemm_grid, 256>>>(hC, w1t, b1, hB, HID, HID);
    // layer 2
    aggregate_h_kernel<HID><<<agg_blocks, 256>>>(hB, hC);
    gemm_f16_bias_relu<false><<<gemm_grid, 256>>>(hC, w2t, b2, hB, HID, HID);

    // pool
    pool_kernel<<<N_GRAPHS, 128>>>(hB, out);
}

// round 16
// speedup vs baseline: 1.3332x; 1.0019x over previous
#include <cuda_runtime.h>
#include <cuda_fp16.h>
#include <cstdint>

// Problem constants
#define N_NODES   50000
#define N_EDGES   800000
#define N_TOT     850000      // edges + self loops
#define IN_CH     128
#define HID       256
#define N_GRAPHS  512
#define M_PAD     50048       // 391 * 128
#define SCAN_NB   196         // ceil(50000/256)
#define NC4       (N_NODES * IN_CH / 4)   // 1,600,000 float4 chunks of x

// ---------------- scratch (device globals; no allocation allowed) -------------
__device__ __half g_xh[(size_t)N_NODES * IN_CH];   // dinv-scaled x in fp16
__device__ __half g_hA[(size_t)M_PAD * IN_CH];     // aggregated input
__device__ __half g_hB[(size_t)M_PAD * HID];       // gemm outputs (ping)
__device__ __half g_hC[(size_t)M_PAD * HID];       // aggregated hidden (pong)
__device__ __half g_w0t[HID * IN_CH];              // W0^T [256][128] fp16
__device__ __half g_w1t[HID * HID];                // W1^T
__device__ __half g_w2t[HID * HID];                // W2^T
__device__ int   g_deg[N_NODES];                   // zero at launch start & end
__device__ float g_dinv[N_NODES];
__device__ int   g_rowptr[N_NODES + 1];
__device__ int   g_cursor[N_NODES];
__device__ int   g_col[N_TOT];
__device__ int   g_gstart[N_GRAPHS + 1];
__device__ int   g_psum[SCAN_NB + 4];

// ---------------- setup: degree count + W transposes + graph ranges ------------
// Edge counting: 2 edges per thread (independent atomic chains).
__global__ void setup_kernel(const float* __restrict__ W0,
                             const float* __restrict__ W1,
                             const float* __restrict__ W2,
                             const int* __restrict__ dst,
                             const int* __restrict__ batch) {
    int i = blockIdx.x * blockDim.x + threadIdx.x;
    int e0 = i * 2;
    if (e0 < N_EDGES)     atomicAdd(&g_deg[dst[e0]], 1);
    if (e0 + 1 < N_EDGES) atomicAdd(&g_deg[dst[e0 + 1]], 1);
    if (i < HID * IN_CH) {                              // W0^T
        int n = i / IN_CH, k = i % IN_CH;
        g_w0t[i] = __float2half(W0[(size_t)k * HID + n]);
    }
    if (i < HID * HID) {                                // W1^T, W2^T
        int n = i / HID, k = i % HID;
        g_w1t[i] = __float2half(W1[(size_t)k * HID + n]);
        g_w2t[i] = __float2half(W2[(size_t)k * HID + n]);
    }
    if (i <= N_GRAPHS) {                                // graph ranges
        int lo = 0, hi = N_NODES;
        while (lo < hi) {
            int mid = (lo + hi) >> 1;
            if (batch[mid] < i) lo = mid + 1; else hi = mid;
        }
        g_gstart[i] = lo;
    }
}

// block sums for scan + dinv.  Effective degree = g_deg + 1 (self loop).
__global__ void bsum_dinv_kernel() {
    int b = blockIdx.x, t = threadIdx.x;
    int idx = b * 256 + t;
    int d = (idx < N_NODES) ? (g_deg[idx] + 1) : 0;
    if (idx < N_NODES) g_dinv[idx] = rsqrtf((float)d);
    int v = d;
    #pragma unroll
    for (int off = 16; off > 0; off >>= 1)
        v += __shfl_down_sync(0xffffffffu, v, off);
    __shared__ int ws[8];
    if ((t & 31) == 0) ws[t >> 5] = v;
    __syncthreads();
    if (t == 0) {
        int s = 0;
        #pragma unroll
        for (int i = 0; i < 8; i++) s += ws[i];
        g_psum[b] = s;
    }
}

// per-block scan; block offset = inline sum of partials < b; resets g_deg.
__global__ void scan_write_kernel() {
    int b = blockIdx.x, t = threadIdx.x, lane = t & 31, w = t >> 5;
    int contrib = (t < b) ? g_psum[t] : 0;
    #pragma unroll
    for (int off = 16; off > 0; off >>= 1)
        contrib += __shfl_down_sync(0xffffffffu, contrib, off);
    __shared__ int rs[8];
    __shared__ int off_s;
    if ((t & 31) == 0) rs[t >> 5] = contrib;
    __syncthreads();
    if (t == 0) {
        int s = 0;
        #pragma unroll
        for (int i = 0; i < 8; i++) s += rs[i];
        off_s = s;
    }
    int idx = b * 256 + t;
    int v = (idx < N_NODES) ? (g_deg[idx] + 1) : 0;
    if (idx < N_NODES) g_deg[idx] = 0;      // restore invariant for next launch
    int x = v;
    #pragma unroll
    for (int off = 1; off < 32; off <<= 1) {
        int y = __shfl_up_sync(0xffffffffu, x, off);
        if (lane >= off) x += y;
    }
    __shared__ int wsum[8];
    if (lane == 31) wsum[w] = x;
    __syncthreads();
    if (t == 0) {
        int run = 0;
        #pragma unroll
        for (int i = 0; i < 8; i++) { int tmp = wsum[i]; wsum[i] = run; run += tmp; }
    }
    __syncthreads();
    int excl = off_s + x + wsum[w] - v;
    if (idx < N_NODES) { g_rowptr[idx] = excl; g_cursor[idx] = excl; }
    if (b == 0 && t == 0) g_rowptr[N_NODES] = N_TOT;
}

// edge/self-loop placement (2 per thread) + dinv-scaled x conversion, one launch
__global__ void place_conv_kernel(const int* __restrict__ src,
                                  const int* __restrict__ dst,
                                  const float* __restrict__ x) {
    int i = blockIdx.x * blockDim.x + threadIdx.x;
    int e0 = i * 2;
    #pragma unroll
    for (int j = 0; j < 2; j++) {
        int e = e0 + j;
        if (e < N_TOT) {
            if (e < N_EDGES) {
                int s = src[e], d = dst[e];
                int pos = atomicAdd(&g_cursor[d], 1);
                g_col[pos] = s;
            } else {
                int v = e - N_EDGES;
                int pos = atomicAdd(&g_cursor[v], 1);
                g_col[pos] = v;
            }
        }
    }
    if (i < NC4) {                       // y[v] = dinv[v] * x[v]  -> fp16
        int row = i >> 5;                // 32 float4 chunks per 128-ch row
        float s = g_dinv[row];
        float4 v = *(const float4*)(x + (size_t)i * 4);
        __half2 h0 = __float22half2_rn(make_float2(v.x * s, v.y * s));
        __half2 h1 = __float22half2_rn(make_float2(v.z * s, v.w * s));
        *(uint2*)(&g_xh[(size_t)i * 4]) = make_uint2(
            *(const unsigned*)&h0, *(const unsigned*)&h1);
    }
}

// ---------------- aggregation: out[v] = dinv[v] * sum_{col} y[col] -------------
// unroll-8 with explicit load phase: 8 independent 16B gathers in flight.
template <int C>
__global__ void __launch_bounds__(256)
aggregate_h_kernel(const __half* __restrict__ x, __half* __restrict__ out) {
    int warp = (blockIdx.x * blockDim.x + threadIdx.x) >> 5;
    int lane = threadIdx.x & 31;
    if (warp >= N_NODES) return;
    constexpr int V = C / 32;                        // halfs per lane: 4 or 8
    float acc[V];
    #pragma unroll
    for (int q = 0; q < V; q++) acc[q] = 0.f;
    int s = g_rowptr[warp], e = g_rowptr[warp + 1];

    if constexpr (V == 8) {
        const __half* base = x + lane * 8;
        auto addu = [&](uint4 u) {
            __half2 h0 = *(__half2*)&u.x, h1 = *(__half2*)&u.y;
            __half2 h2 = *(__half2*)&u.z, h3 = *(__half2*)&u.w;
            float2 f0 = __half22float2(h0), f1 = __half22float2(h1);
            float2 f2 = __half22float2(h2), f3 = __half22float2(h3);
            acc[0] += f0.x; acc[1] += f0.y; acc[2] += f1.x; acc[3] += f1.y;
            acc[4] += f2.x; acc[5] += f2.y; acc[6] += f3.x; acc[7] += f3.y;
        };
        int i = s;
        for (; i + 8 <= e; i += 8) {
            int cc[8];
            #pragma unroll
            for (int j = 0; j < 8; j++) cc[j] = g_col[i + j];
            uint4 u[8];
            #pragma unroll
            for (int j = 0; j < 8; j++)
                u[j] = __ldg((const uint4*)(base + (size_t)cc[j] * C));
            #pragma unroll
            for (int j = 0; j < 8; j++) addu(u[j]);
        }
        for (; i + 2 <= e; i += 2) {
            int c0 = g_col[i], c1 = g_col[i + 1];
            uint4 u0 = __ldg((const uint4*)(base + (size_t)c0 * C));
            uint4 u1 = __ldg((const uint4*)(base + (size_t)c1 * C));
            addu(u0); addu(u1);
        }
        if (i < e)
            addu(__ldg((const uint4*)(base + (size_t)g_col[i] * C)));
    } else {
        const __half* base = x + lane * 4;
        auto addu = [&](uint2 u) {
            __half2 h0 = *(__half2*)&u.x, h1 = *(__half2*)&u.y;
            float2 f0 = __half22float2(h0), f1 = __half22float2(h1);
            acc[0] += f0.x; acc[1] += f0.y; acc[2] += f1.x; acc[3] += f1.y;
        };
        int i = s;
        for (; i + 8 <= e; i += 8) {
            int cc[8];
            #pragma unroll
            for (int j = 0; j < 8; j++) cc[j] = g_col[i + j];
            uint2 u[8];
            #pragma unroll
            for (int j = 0; j < 8; j++)
                u[j] = __ldg((const uint2*)(base + (size_t)cc[j] * C));
            #pragma unroll
            for (int j = 0; j < 8; j++) addu(u[j]);
        }
        for (; i + 2 <= e; i += 2) {
            int c0 = g_col[i], c1 = g_col[i + 1];
            uint2 u0 = __ldg((const uint2*)(base + (size_t)c0 * C));
            uint2 u1 = __ldg((const uint2*)(base + (size_t)c1 * C));
            addu(u0); addu(u1);
        }
        if (i < e)
            addu(__ldg((const uint2*)(base + (size_t)g_col[i] * C)));
    }

    float sc = g_dinv[warp];
    __half* orow = out + (size_t)warp * C + lane * V;
    if constexpr (V == 4) {
        __half2 o0 = __float22half2_rn(make_float2(acc[0] * sc, acc[1] * sc));
        __half2 o1 = __float22half2_rn(make_float2(acc[2] * sc, acc[3] * sc));
        *(uint2*)orow = make_uint2(*(unsigned*)&o0, *(unsigned*)&o1);
    } else {
        __half2 o0 = __float22half2_rn(make_float2(acc[0] * sc, acc[1] * sc));
        __half2 o1 = __float22half2_rn(make_float2(acc[2] * sc, acc[3] * sc));
        __half2 o2 = __float22half2_rn(make_float2(acc[4] * sc, acc[5] * sc));
        __half2 o3 = __float22half2_rn(make_float2(acc[6] * sc, acc[7] * sc));
        *(uint4*)orow = make_uint4(*(unsigned*)&o0, *(unsigned*)&o1,
                                   *(unsigned*)&o2, *(unsigned*)&o3);
    }
}

// ---------------- GEMM: fp16 MMA, cp.async double-buffered ---------------------
// SCALED=true: store dinv[row]*relu(acc+b) (feeds next aggregation).
#define BM 128
#define BN 128
#define BKH 32
#define HSTR 40   // half stride (80 B, 16B-aligned, conflict-free fragment LDS)

#define MMA_F16(d, a0, a1, a2, a3, b0, b1)                                    \
    asm volatile(                                                             \
        "mma.sync.aligned.m16n8k16.row.col.f32.f16.f16.f32 "                  \
        "{%0,%1,%2,%3}, {%4,%5,%6,%7}, {%8,%9}, {%0,%1,%2,%3};"               \
        : "+f"((d)[0]), "+f"((d)[1]), "+f"((d)[2]), "+f"((d)[3])              \
        : "r"(a0), "r"(a1), "r"(a2), "r"(a3), "r"(b0), "r"(b1))

__device__ __forceinline__ void cpa16(void* sm, const void* gm) {
    uint32_t sa = (uint32_t)__cvta_generic_to_shared(sm);
    asm volatile("cp.async.cg.shared.global [%0], [%1], 16;" :: "r"(sa), "l"(gm));
}

template <bool SCALED>
__global__ void __launch_bounds__(256)
gemm_f16_bias_relu(const __half* __restrict__ A, const __half* __restrict__ Wt,
                   const float* __restrict__ bias, __half* __restrict__ C,
                   int K, int N) {
    __shared__ __align__(16) __half As[2][BM][HSTR];   // [stage][m][k]
    __shared__ __align__(16) __half Bs[2][BN][HSTR];   // [stage][n][k]
    int tid = threadIdx.x, lane = tid & 31, wid = tid >> 5;
    int wm = (wid >> 2) * 64;            // 0 or 64
    int wn = (wid & 3) * 32;             // 0..96
    int g = lane >> 2;                   // 0..7
    int t = lane & 3;                    // 0..3

    float acc[4][4][4];
    #pragma unroll
    for (int i = 0; i < 4; i++)
        #pragma unroll
        for (int j = 0; j < 4; j++)
            #pragma unroll
            for (int q = 0; q < 4; q++) acc[i][j][q] = 0.f;

    const __half* Ablk = A + (size_t)blockIdx.y * BM * K;
    const __half* Wblk = Wt + (size_t)blockIdx.x * BN * K;

    int ldr = tid >> 1;                  // 0..127
    int ldc = (tid & 1) * 16;            // 0 or 16 (halfs)

    int niter = K / BKH;

    auto issue = [&](int it) {
        int st = it & 1;
        int k0 = it * BKH;
        const __half* ap = Ablk + (size_t)ldr * K + k0 + ldc;
        cpa16(&As[st][ldr][ldc],     ap);
        cpa16(&As[st][ldr][ldc + 8], ap + 8);
        const __half* bp = Wblk + (size_t)ldr * K + k0 + ldc;
        cpa16(&Bs[st][ldr][ldc],     bp);
        cpa16(&Bs[st][ldr][ldc + 8], bp + 8);
        asm volatile("cp.async.commit_group;");
    };

    issue(0);
    for (int it = 0; it < niter; it++) {
        if (it + 1 < niter) {
            issue(it + 1);
            asm volatile("cp.async.wait_group 1;");
        } else {
            asm volatile("cp.async.wait_group 0;");
        }
        __syncthreads();
        int st = it & 1;
        #pragma unroll
        for (int kk = 0; kk < BKH; kk += 16) {
            int kbase = kk + 2 * t;
            uint a0[4], a1[4], a2[4], a3[4];
            #pragma unroll
            for (int mt = 0; mt < 4; mt++) {
                int r = wm + mt * 16 + g;
                a0[mt] = *(const uint*)&As[st][r    ][kbase];
                a1[mt] = *(const uint*)&As[st][r + 8][kbase];
                a2[mt] = *(const uint*)&As[st][r    ][kbase + 8];
                a3[mt] = *(const uint*)&As[st][r + 8][kbase + 8];
            }
            uint b0[4], b1[4];
            #pragma unroll
            for (int nt = 0; nt < 4; nt++) {
                int n = wn + nt * 8 + g;
                b0[nt] = *(const uint*)&Bs[st][n][kbase];
                b1[nt] = *(const uint*)&Bs[st][n][kbase + 8];
            }
            #pragma unroll
            for (int mt = 0; mt < 4; mt++)
                #pragma unroll
                for (int nt = 0; nt < 4; nt++)
                    MMA_F16(acc[mt][nt], a0[mt], a1[mt], a2[mt], a3[mt],
                            b0[nt], b1[nt]);
        }
        __syncthreads();
    }

    // epilogue: bias + relu (+ optional dinv row scale), fp16 stores
    #pragma unroll
    for (int mt = 0; mt < 4; mt++) {
        int row0 = blockIdx.y * BM + wm + mt * 16 + g;
        float s0 = 1.f, s1 = 1.f;
        if (SCALED) {
            s0 = (row0     < N_NODES) ? g_dinv[row0]     : 0.f;
            s1 = (row0 + 8 < N_NODES) ? g_dinv[row0 + 8] : 0.f;
        }
        #pragma unroll
        for (int nt = 0; nt < 4; nt++) {
            int col = blockIdx.x * BN + wn + nt * 8 + 2 * t;
            float2 bb = *(const float2*)(bias + col);
            __half2 o0 = __float22half2_rn(make_float2(
                fmaxf(acc[mt][nt][0] + bb.x, 0.f) * s0,
                fmaxf(acc[mt][nt][1] + bb.y, 0.f) * s0));
            __half2 o1 = __float22half2_rn(make_float2(
                fmaxf(acc[mt][nt][2] + bb.x, 0.f) * s1,
                fmaxf(acc[mt][nt][3] + bb.y, 0.f) * s1));
            *(unsigned*)(C + (size_t)row0 * N + col)       = *(unsigned*)&o0;
            *(unsigned*)(C + (size_t)(row0 + 8) * N + col) = *(unsigned*)&o1;
        }
    }
}

// ---------------- pooling (128 threads x 2 channels via half2) -----------------
__global__ void pool_kernel(const __half* __restrict__ h, float* __restrict__ out) {
    int gph = blockIdx.x;
    int c2 = threadIdx.x;                 // 128 half2 channels
    int s = g_gstart[gph], e = g_gstart[gph + 1];
    float accx = 0.f, accy = 0.f;
    for (int v = s; v < e; v++) {
        __half2 hv = *(const __half2*)(h + (size_t)v * HID + c2 * 2);
        float2 f = __half22float2(hv);
        accx += f.x; accy += f.y;
    }
    *(float2*)(out + (size_t)gph * HID + c2 * 2) = make_float2(accx, accy);
}

// ---------------- launch -------------------------------------------------------
extern "C" void kernel_launch(void* const* d_in, const int* in_sizes, int n_in,
                              void* d_out, int out_size) {
    const float* x   = (const float*)d_in[0];
    const float* W0  = (const float*)d_in[1];
    const float* b0  = (const float*)d_in[2];
    const float* W1  = (const float*)d_in[3];
    const float* b1  = (const float*)d_in[4];
    const float* W2  = (const float*)d_in[5];
    const float* b2  = (const float*)d_in[6];
    const int*   ei  = (const int*)d_in[7];
    const int*   bat = (const int*)d_in[8];
    float* out = (float*)d_out;

    const int* src = ei;
    const int* dst = ei + N_EDGES;

    __half* xh;  cudaGetSymbolAddress((void**)&xh,  g_xh);
    __half* hA;  cudaGetSymbolAddress((void**)&hA,  g_hA);
    __half* hB;  cudaGetSymbolAddress((void**)&hB,  g_hB);
    __half* hC;  cudaGetSymbolAddress((void**)&hC,  g_hC);
    __half* w0t; cudaGetSymbolAddress((void**)&w0t, g_w0t);
    __half* w1t; cudaGetSymbolAddress((void**)&w1t, g_w1t);
    __half* w2t; cudaGetSymbolAddress((void**)&w2t, g_w2t);

    // prep: setup(count+Wt+ranges) -> bsum+dinv -> scan(+deg reset) -> place+conv
    setup_kernel<<<(N_EDGES / 2 + 255) / 256, 256>>>(W0, W1, W2, dst, bat);
    bsum_dinv_kernel<<<SCAN_NB, 256>>>();
    scan_write_kernel<<<SCAN_NB, 256>>>();
    place_conv_kernel<<<(NC4 + 255) / 256, 256>>>(src, dst, x);

    dim3 gemm_grid(HID / BN, M_PAD / BM);   // (2, 391)
    int agg_blocks = (N_NODES * 32 + 255) / 256;

    // layer 0
    aggregate_h_kernel<IN_CH><<<agg_blocks, 256>>>(xh, hA);
    gemm_f16_bias_relu<true><<<gemm_grid, 256>>>(hA, w0t, b0, hB, IN_CH, HID);
    // layer 1
    aggregate_h_kernel<HID><<<agg_blocks, 256>>>(hB, hC);
    gemm_f16_bias_relu<true><<<gemm_grid, 256>>>(hC, w1t, b1, hB, HID, HID);
    // layer 2
    aggregate_h_kernel<HID><<<agg_blocks, 256>>>(hB, hC);
    gemm_f16_bias_relu<false><<<gemm_grid, 256>>>(hC, w2t, b2, hB, HID, HID);

    // pool
    pool_kernel<<<N_GRAPHS, 128>>>(hB, out);
}